// round 1
// baseline (speedup 1.0000x reference)
#include <cuda_runtime.h>
#include <cuda_bf16.h>
#include <math.h>

// Shapes: B=4, N=256, F=64, H=256, A=16, T=3
#define Bn 4
#define Nn 256
#define Fn 64
#define Hn 256
#define An 16
#define Tn 3
#define BN (Bn*Nn)   // 1024

// ---------------- scratch (device globals; no malloc allowed) ----------------
__device__ float d_h   [BN*Hn];     // node state
__device__ float d_t   [BN*Hn];     // pre-MLP hidden
__device__ float d_hi  [BN*Hn];
__device__ float d_hj  [BN*Hn];
__device__ float d_agg0[BN*Hn];     // sum_j adj * relu(hi+hj+b1)
__device__ float d_deg [BN];
__device__ float d_gi  [BN*3*Hn];
__device__ float d_gh  [BN*3*Hn];
__device__ float d_Wc  [Hn*3*Hn];   // msg_W2 @ gru_Wih
__device__ float d_bc  [3*Hn];      // msg_b2 @ gru_Wih

// ---------------- generic fp32 GEMM: C = f(A@B + bias + rowS*colV) -----------
// A: MxK row-major, B: KxN row-major, 64x64 tile, 256 thr, 4x4 per thread.
// All M,N multiples of 64; K multiple of 16 (true for every call here).
__global__ void gemm64(const float* __restrict__ A, const float* __restrict__ Bm,
                       const float* __restrict__ bias, float* __restrict__ C,
                       int M, int N, int K, int doRelu,
                       const float* __restrict__ rowS, const float* __restrict__ colV)
{
    __shared__ float As[16][65];                 // [k][m], padded vs bank conflicts
    __shared__ __align__(16) float Bs[16][64];   // [k][n]

    int tid = threadIdx.x;
    int tx = tid & 15, ty = tid >> 4;
    int row0 = blockIdx.y * 64, col0 = blockIdx.x * 64;

    float acc[4][4];
    #pragma unroll
    for (int i = 0; i < 4; i++)
        #pragma unroll
        for (int j = 0; j < 4; j++) acc[i][j] = 0.f;

    int arow = tid >> 2;           // 0..63
    int akk  = (tid & 3) << 2;     // 0,4,8,12
    int brow = tid >> 4;           // 0..15
    int bcol = (tid & 15) << 2;    // 0..60

    for (int k0 = 0; k0 < K; k0 += 16) {
        float4 av = *(const float4*)(A + (size_t)(row0 + arow) * K + k0 + akk);
        As[akk + 0][arow] = av.x;
        As[akk + 1][arow] = av.y;
        As[akk + 2][arow] = av.z;
        As[akk + 3][arow] = av.w;
        float4 bv = *(const float4*)(Bm + (size_t)(k0 + brow) * N + col0 + bcol);
        *(float4*)&Bs[brow][bcol] = bv;
        __syncthreads();
        #pragma unroll
        for (int k = 0; k < 16; k++) {
            float a0 = As[k][ty * 4 + 0];
            float a1 = As[k][ty * 4 + 1];
            float a2 = As[k][ty * 4 + 2];
            float a3 = As[k][ty * 4 + 3];
            float4 b4 = *(float4*)&Bs[k][tx * 4];
            acc[0][0] += a0 * b4.x; acc[0][1] += a0 * b4.y; acc[0][2] += a0 * b4.z; acc[0][3] += a0 * b4.w;
            acc[1][0] += a1 * b4.x; acc[1][1] += a1 * b4.y; acc[1][2] += a1 * b4.z; acc[1][3] += a1 * b4.w;
            acc[2][0] += a2 * b4.x; acc[2][1] += a2 * b4.y; acc[2][2] += a2 * b4.z; acc[2][3] += a2 * b4.w;
            acc[3][0] += a3 * b4.x; acc[3][1] += a3 * b4.y; acc[3][2] += a3 * b4.z; acc[3][3] += a3 * b4.w;
        }
        __syncthreads();
    }

    #pragma unroll
    for (int i = 0; i < 4; i++) {
        int r = row0 + ty * 4 + i;
        float rs = rowS ? rowS[r] : 0.f;
        #pragma unroll
        for (int j = 0; j < 4; j++) {
            int c = col0 + tx * 4 + j;
            float v = acc[i][j];
            if (bias) v += bias[c];
            if (rowS) v += rs * colV[c];
            if (doRelu) v = fmaxf(v, 0.f);
            C[(size_t)r * N + c] = v;
        }
    }
}

// ---------------- E-aggregation: agg0[b,i,h] = sum_j adj[b,i,j]*relu(hi+hj+b1)
#define IT 8
__global__ void eagg(const float* __restrict__ hi, const float* __restrict__ hj,
                     const int* __restrict__ adj, const float* __restrict__ b1,
                     float* __restrict__ agg0, float* __restrict__ deg)
{
    int b  = blockIdx.y;
    int i0 = blockIdx.x * IT;
    int h  = threadIdx.x;

    __shared__ float adjf[IT][Nn];

    float hir[IT], acc[IT];
    float bv = b1[h];
    #pragma unroll
    for (int t = 0; t < IT; t++) {
        adjf[t][h] = (float)adj[((size_t)(b * Nn + i0 + t)) * Nn + h];
        hir[t] = hi[((size_t)(b * Nn + i0 + t)) * Hn + h] + bv;
        acc[t] = 0.f;
    }
    __syncthreads();

    const float* hjb = hj + (size_t)b * Nn * Hn;
    #pragma unroll 4
    for (int j = 0; j < Nn; j++) {
        float hjv = hjb[(size_t)j * Hn + h];
        #pragma unroll
        for (int t = 0; t < IT; t++)
            acc[t] += adjf[t][j] * fmaxf(hir[t] + hjv, 0.f);
    }

    #pragma unroll
    for (int t = 0; t < IT; t++)
        agg0[((size_t)(b * Nn + i0 + t)) * Hn + h] = acc[t];

    if (h < IT) {
        float s = 0.f;
        for (int j = 0; j < Nn; j++) s += adjf[h][j];
        deg[b * Nn + i0 + h] = s;
    }
}

// ---------------- bc = msg_b2 @ gru_Wih -------------------------------------
__global__ void bck(const float* __restrict__ b2, const float* __restrict__ Wih,
                    float* __restrict__ bc)
{
    int n = blockIdx.x * 256 + threadIdx.x;   // 0..767
    float s = 0.f;
    for (int k = 0; k < Hn; k++) s += b2[k] * Wih[(size_t)k * (3 * Hn) + n];
    bc[n] = s;
}

// ---------------- GRU elementwise update ------------------------------------
__global__ void gru(const float* __restrict__ gi, const float* __restrict__ gh,
                    float* __restrict__ h)
{
    int idx = blockIdx.x * 256 + threadIdx.x;   // over BN*Hn
    int m = idx >> 8, c = idx & 255;
    const float* gim = gi + (size_t)m * (3 * Hn);
    const float* ghm = gh + (size_t)m * (3 * Hn);
    float ir = gim[c], iz = gim[c + Hn], in = gim[c + 2 * Hn];
    float hr = ghm[c], hz = ghm[c + Hn], hn = ghm[c + 2 * Hn];
    float r = 1.f / (1.f + __expf(-(ir + hr)));
    float z = 1.f / (1.f + __expf(-(iz + hz)));
    float n = tanhf(in + r * hn);
    float hv = h[idx];
    h[idx] = (1.f - z) * n + z * hv;
}

// ---------------- readout: q = relu(sum_i(h) @ W1 + b1) @ W2 + b2 -----------
__global__ void readout(const float* __restrict__ h,
                        const float* __restrict__ W1, const float* __restrict__ b1,
                        const float* __restrict__ W2, const float* __restrict__ b2,
                        float* __restrict__ out)
{
    __shared__ float gsh[Bn][Hn];
    __shared__ float hsh[Bn][Hn];
    int t = threadIdx.x;

    for (int b = 0; b < Bn; b++) {
        float s = 0.f;
        for (int i = 0; i < Nn; i++)
            s += h[((size_t)(b * Nn + i)) * Hn + t];
        gsh[b][t] = s;
    }
    __syncthreads();

    for (int b = 0; b < Bn; b++) {
        float s = b1[t];
        for (int k = 0; k < Hn; k++)
            s += gsh[b][k] * W1[(size_t)k * Hn + t];
        hsh[b][t] = fmaxf(s, 0.f);
    }
    __syncthreads();

    if (t < Bn * An) {
        int b = t >> 4, a = t & 15;
        float s = b2[a];
        for (int k = 0; k < Hn; k++)
            s += hsh[b][k] * W2[(size_t)k * An + a];
        out[b * An + a] = s;
    }
}

// ---------------- host launch ------------------------------------------------
extern "C" void kernel_launch(void* const* d_in, const int* in_sizes, int n_in,
                              void* d_out, int out_size)
{
    const float* X       = (const float*)d_in[0];
    const int*   adj     = (const int*)  d_in[1];
    const float* pre_W1  = (const float*)d_in[2];
    const float* pre_b1  = (const float*)d_in[3];
    const float* pre_W2  = (const float*)d_in[4];
    const float* pre_b2  = (const float*)d_in[5];
    const float* msg_W1  = (const float*)d_in[6];
    const float* msg_b1  = (const float*)d_in[7];
    const float* msg_W2  = (const float*)d_in[8];
    const float* msg_b2  = (const float*)d_in[9];
    const float* gru_Wih = (const float*)d_in[10];
    const float* gru_Whh = (const float*)d_in[11];
    const float* gru_bih = (const float*)d_in[12];
    const float* gru_bhh = (const float*)d_in[13];
    const float* ro_W1   = (const float*)d_in[14];
    const float* ro_b1   = (const float*)d_in[15];
    const float* ro_W2   = (const float*)d_in[16];
    const float* ro_b2   = (const float*)d_in[17];

    float *h, *t, *hi, *hj, *agg0, *deg, *gi, *gh, *Wc, *bc;
    cudaGetSymbolAddress((void**)&h,    d_h);
    cudaGetSymbolAddress((void**)&t,    d_t);
    cudaGetSymbolAddress((void**)&hi,   d_hi);
    cudaGetSymbolAddress((void**)&hj,   d_hj);
    cudaGetSymbolAddress((void**)&agg0, d_agg0);
    cudaGetSymbolAddress((void**)&deg,  d_deg);
    cudaGetSymbolAddress((void**)&gi,   d_gi);
    cudaGetSymbolAddress((void**)&gh,   d_gh);
    cudaGetSymbolAddress((void**)&Wc,   d_Wc);
    cudaGetSymbolAddress((void**)&bc,   d_bc);

    // pre-MLP: h = relu(X@pre_W1+b1) @ pre_W2 + b2
    gemm64<<<dim3(Hn/64, BN/64), 256>>>(X, pre_W1, pre_b1, t, BN, Hn, Fn, 1, nullptr, nullptr);
    gemm64<<<dim3(Hn/64, BN/64), 256>>>(t, pre_W2, pre_b2, h, BN, Hn, Hn, 0, nullptr, nullptr);

    // Wc = msg_W2 @ gru_Wih ; bc = msg_b2 @ gru_Wih
    gemm64<<<dim3(3*Hn/64, Hn/64), 256>>>(msg_W2, gru_Wih, nullptr, Wc, Hn, 3*Hn, Hn, 0, nullptr, nullptr);
    bck<<<3, 256>>>(msg_b2, gru_Wih, bc);

    for (int it = 0; it < Tn; it++) {
        // hi = h @ W1_i ; hj = h @ W1_j
        gemm64<<<dim3(Hn/64, BN/64), 256>>>(h, msg_W1,           nullptr, hi, BN, Hn, Hn, 0, nullptr, nullptr);
        gemm64<<<dim3(Hn/64, BN/64), 256>>>(h, msg_W1 + Hn*Hn,   nullptr, hj, BN, Hn, Hn, 0, nullptr, nullptr);
        // agg0, deg
        eagg<<<dim3(Nn/IT, Bn), 256>>>(hi, hj, adj, msg_b1, agg0, deg);
        // gi = agg0 @ Wc + deg*bc + bih    (== (agg0@W2 + deg*b2) @ Wih + bih)
        gemm64<<<dim3(3*Hn/64, BN/64), 256>>>(agg0, Wc, gru_bih, gi, BN, 3*Hn, Hn, 0, deg, bc);
        // gh = h @ Whh + bhh
        gemm64<<<dim3(3*Hn/64, BN/64), 256>>>(h, gru_Whh, gru_bhh, gh, BN, 3*Hn, Hn, 0, nullptr, nullptr);
        // GRU update (in place on h)
        gru<<<BN, 256>>>(gi, gh, h);
    }

    readout<<<1, 256>>>(h, ro_W1, ro_b1, ro_W2, ro_b2, (float*)d_out);
}

// round 2
// speedup vs baseline: 1.2133x; 1.2133x over previous
#include <cuda_runtime.h>
#include <cuda_bf16.h>
#include <math.h>

// Shapes: B=4, N=256, F=64, H=256, A=16, T=3
#define Bn 4
#define Nn 256
#define Fn 64
#define Hn 256
#define An 16
#define Tn 3
#define BN (Bn*Nn)       // 1024
#define NC 1280          // fused output cols: 256(hi) + 256(hj) + 768(gh)

// ---------------- scratch (device globals; no malloc allowed) ----------------
__device__ float d_h   [BN*Hn];      // node state
__device__ float d_big [BN*NC];      // [hi | hj | gh] fused; also reused as pre-MLP temp
__device__ float d_agg0[BN*Hn];
__device__ float d_deg [BN];
__device__ float d_gi  [BN*3*Hn];
__device__ float d_Wc  [Hn*3*Hn];    // msg_W2 @ gru_Wih
__device__ float d_bc  [3*Hn];       // msg_b2 @ gru_Wih
__device__ float d_Wcat[Hn*NC];      // [W1_i | W1_j | Whh]
__device__ float d_bcat[NC];         // [msg_b1 | 0 | gru_bhh]

// ---------------- fp32 GEMM: C = f(A@B + bias + rowS*colV) -------------------
// A: MxK row-major, B: KxN row-major. Tile 128x64, 256 thr, 8x4 per thread.
// M multiple of 128, N multiple of 64, K multiple of 16.
__global__ void gemm128(const float* __restrict__ A, const float* __restrict__ Bm,
                        const float* __restrict__ bias, float* __restrict__ C,
                        int M, int N, int K, int doRelu,
                        const float* __restrict__ rowS, const float* __restrict__ colV)
{
    __shared__ float As[16][132];               // [k][m], 132 stride: 16B-aligned rows
    __shared__ __align__(16) float Bs[16][64];  // [k][n]

    int tid = threadIdx.x;
    int tx = tid & 15, ty = tid >> 4;           // tx: n-group, ty: m-group
    int row0 = blockIdx.y * 128, col0 = blockIdx.x * 64;

    // A load: m = tid>>1 (0..127), kg = (tid&1)*8 -> two float4 along k
    int am = tid >> 1, akg = (tid & 1) << 3;
    // B load: k = tid>>4 (0..15), n = (tid&15)*4 -> one float4 along n
    int bk = tid >> 4, bn = (tid & 15) << 2;

    const float* Aptr = A + (size_t)(row0 + am) * K + akg;
    const float* Bptr = Bm + (size_t)bk * N + col0 + bn;

    float acc[8][4];
    #pragma unroll
    for (int i = 0; i < 8; i++)
        #pragma unroll
        for (int j = 0; j < 4; j++) acc[i][j] = 0.f;

    float4 a0 = *(const float4*)(Aptr);
    float4 a1 = *(const float4*)(Aptr + 4);
    float4 b0 = *(const float4*)(Bptr);

    int nch = K >> 4;
    for (int ch = 0; ch < nch; ch++) {
        As[akg+0][am] = a0.x; As[akg+1][am] = a0.y; As[akg+2][am] = a0.z; As[akg+3][am] = a0.w;
        As[akg+4][am] = a1.x; As[akg+5][am] = a1.y; As[akg+6][am] = a1.z; As[akg+7][am] = a1.w;
        *(float4*)&Bs[bk][bn] = b0;
        __syncthreads();

        if (ch + 1 < nch) {   // prefetch next chunk into regs during compute
            a0 = *(const float4*)(Aptr + (ch + 1) * 16);
            a1 = *(const float4*)(Aptr + (ch + 1) * 16 + 4);
            b0 = *(const float4*)(Bptr + (size_t)(ch + 1) * 16 * N);
        }

        #pragma unroll
        for (int k = 0; k < 16; k++) {
            float4 aL = *(float4*)&As[k][ty * 4];
            float4 aH = *(float4*)&As[k][64 + ty * 4];
            float4 bb = *(float4*)&Bs[k][tx * 4];
            acc[0][0] += aL.x*bb.x; acc[0][1] += aL.x*bb.y; acc[0][2] += aL.x*bb.z; acc[0][3] += aL.x*bb.w;
            acc[1][0] += aL.y*bb.x; acc[1][1] += aL.y*bb.y; acc[1][2] += aL.y*bb.z; acc[1][3] += aL.y*bb.w;
            acc[2][0] += aL.z*bb.x; acc[2][1] += aL.z*bb.y; acc[2][2] += aL.z*bb.z; acc[2][3] += aL.z*bb.w;
            acc[3][0] += aL.w*bb.x; acc[3][1] += aL.w*bb.y; acc[3][2] += aL.w*bb.z; acc[3][3] += aL.w*bb.w;
            acc[4][0] += aH.x*bb.x; acc[4][1] += aH.x*bb.y; acc[4][2] += aH.x*bb.z; acc[4][3] += aH.x*bb.w;
            acc[5][0] += aH.y*bb.x; acc[5][1] += aH.y*bb.y; acc[5][2] += aH.y*bb.z; acc[5][3] += aH.y*bb.w;
            acc[6][0] += aH.z*bb.x; acc[6][1] += aH.z*bb.y; acc[6][2] += aH.z*bb.z; acc[6][3] += aH.z*bb.w;
            acc[7][0] += aH.w*bb.x; acc[7][1] += aH.w*bb.y; acc[7][2] += aH.w*bb.z; acc[7][3] += aH.w*bb.w;
        }
        __syncthreads();
    }

    #pragma unroll
    for (int g = 0; g < 2; g++) {
        #pragma unroll
        for (int i = 0; i < 4; i++) {
            int r = row0 + g * 64 + ty * 4 + i;
            float rs = rowS ? rowS[r] : 0.f;
            #pragma unroll
            for (int j = 0; j < 4; j++) {
                int c = col0 + tx * 4 + j;
                float v = acc[g * 4 + i][j];
                if (bias) v += bias[c];
                if (rowS) v += rs * colV[c];
                if (doRelu) v = fmaxf(v, 0.f);
                C[(size_t)r * N + c] = v;
            }
        }
    }
}

// ---------------- weight repack: Wcat = [W1_i | W1_j | Whh], bcat ------------
__global__ void repack(const float* __restrict__ msgW1, const float* __restrict__ Whh,
                       const float* __restrict__ msgb1, const float* __restrict__ bhh,
                       float* __restrict__ Wcat, float* __restrict__ bcat)
{
    int idx = blockIdx.x * 256 + threadIdx.x;        // over Hn*NC
    int k = idx / NC, n = idx % NC;
    float v;
    if (n < 256)       v = msgW1[(size_t)k * Hn + n];
    else if (n < 512)  v = msgW1[(size_t)(256 + k) * Hn + (n - 256)];
    else               v = Whh[(size_t)k * 768 + (n - 512)];
    Wcat[idx] = v;
    if (idx < NC)
        bcat[idx] = idx < 256 ? msgb1[idx] : (idx < 512 ? 0.f : bhh[idx - 512]);
}

// ---------------- E-aggregation: agg0[b,i,h] = sum_j adj*relu(hi'+hj) --------
// hi' (= h@W1_i + b1) at big[:,0:256], hj at big[:,256:512]
#define IT 8
__global__ void eagg(const float* __restrict__ big, const int* __restrict__ adj,
                     float* __restrict__ agg0, float* __restrict__ deg)
{
    int b  = blockIdx.y;
    int i0 = blockIdx.x * IT;
    int h  = threadIdx.x;

    __shared__ float adjf[IT][Nn];

    float hir[IT], acc[IT];
    #pragma unroll
    for (int t = 0; t < IT; t++) {
        adjf[t][h] = (float)adj[((size_t)(b * Nn + i0 + t)) * Nn + h];
        hir[t] = big[((size_t)(b * Nn + i0 + t)) * NC + h];
        acc[t] = 0.f;
    }
    __syncthreads();

    const float* hjb = big + (size_t)b * Nn * NC + 256;
    #pragma unroll 4
    for (int j = 0; j < Nn; j++) {
        float hjv = hjb[(size_t)j * NC + h];
        #pragma unroll
        for (int t = 0; t < IT; t++)
            acc[t] += adjf[t][j] * fmaxf(hir[t] + hjv, 0.f);
    }

    #pragma unroll
    for (int t = 0; t < IT; t++)
        agg0[((size_t)(b * Nn + i0 + t)) * Hn + h] = acc[t];

    if (h < IT) {
        float s = 0.f;
        for (int j = 0; j < Nn; j++) s += adjf[h][j];
        deg[b * Nn + i0 + h] = s;
    }
}

// ---------------- bc = msg_b2 @ gru_Wih  (one warp per output) ---------------
__global__ void bck(const float* __restrict__ b2, const float* __restrict__ Wih,
                    float* __restrict__ bc)
{
    int warp = (blockIdx.x * blockDim.x + threadIdx.x) >> 5;   // 0..767
    int lane = threadIdx.x & 31;
    float s = 0.f;
    for (int k = lane; k < Hn; k += 32)
        s += b2[k] * Wih[(size_t)k * 768 + warp];
    #pragma unroll
    for (int o = 16; o; o >>= 1) s += __shfl_xor_sync(0xffffffffu, s, o);
    if (lane == 0) bc[warp] = s;
}

// ---------------- GRU elementwise update ------------------------------------
// gi: BN x 768 (stride 768). gh inside big at cols 512..1279 (stride 1280).
__global__ void gru(const float* __restrict__ gi, const float* __restrict__ big,
                    float* __restrict__ h)
{
    int idx = blockIdx.x * 256 + threadIdx.x;   // over BN*Hn
    int m = idx >> 8, c = idx & 255;
    const float* gim = gi  + (size_t)m * 768;
    const float* ghm = big + (size_t)m * NC + 512;
    float ir = gim[c], iz = gim[c + 256], in = gim[c + 512];
    float hr = ghm[c], hz = ghm[c + 256], hn = ghm[c + 512];
    float r = 1.f / (1.f + __expf(-(ir + hr)));
    float z = 1.f / (1.f + __expf(-(iz + hz)));
    float n = tanhf(in + r * hn);
    float hv = h[idx];
    h[idx] = (1.f - z) * n + z * hv;
}

// ---------------- readout: q = relu(sum_i(h) @ W1 + b1) @ W2 + b2 -----------
__global__ void readout(const float* __restrict__ h,
                        const float* __restrict__ W1, const float* __restrict__ b1,
                        const float* __restrict__ W2, const float* __restrict__ b2,
                        float* __restrict__ out)
{
    __shared__ float gsh[Bn][Hn];
    __shared__ float hsh[Bn][Hn];
    int t = threadIdx.x;

    for (int b = 0; b < Bn; b++) {
        float s = 0.f;
        for (int i = 0; i < Nn; i++)
            s += h[((size_t)(b * Nn + i)) * Hn + t];
        gsh[b][t] = s;
    }
    __syncthreads();

    for (int b = 0; b < Bn; b++) {
        float s = b1[t];
        for (int k = 0; k < Hn; k++)
            s += gsh[b][k] * W1[(size_t)k * Hn + t];
        hsh[b][t] = fmaxf(s, 0.f);
    }
    __syncthreads();

    if (t < Bn * An) {
        int b = t >> 4, a = t & 15;
        float s = b2[a];
        for (int k = 0; k < Hn; k++)
            s += hsh[b][k] * W2[(size_t)k * An + a];
        out[b * An + a] = s;
    }
}

// ---------------- host launch ------------------------------------------------
extern "C" void kernel_launch(void* const* d_in, const int* in_sizes, int n_in,
                              void* d_out, int out_size)
{
    const float* X       = (const float*)d_in[0];
    const int*   adj     = (const int*)  d_in[1];
    const float* pre_W1  = (const float*)d_in[2];
    const float* pre_b1  = (const float*)d_in[3];
    const float* pre_W2  = (const float*)d_in[4];
    const float* pre_b2  = (const float*)d_in[5];
    const float* msg_W1  = (const float*)d_in[6];
    const float* msg_b1  = (const float*)d_in[7];
    const float* msg_W2  = (const float*)d_in[8];
    const float* msg_b2  = (const float*)d_in[9];
    const float* gru_Wih = (const float*)d_in[10];
    const float* gru_Whh = (const float*)d_in[11];
    const float* gru_bih = (const float*)d_in[12];
    const float* gru_bhh = (const float*)d_in[13];
    const float* ro_W1   = (const float*)d_in[14];
    const float* ro_b1   = (const float*)d_in[15];
    const float* ro_W2   = (const float*)d_in[16];
    const float* ro_b2   = (const float*)d_in[17];

    float *h, *big, *agg0, *deg, *gi, *Wc, *bc, *Wcat, *bcat;
    cudaGetSymbolAddress((void**)&h,    d_h);
    cudaGetSymbolAddress((void**)&big,  d_big);
    cudaGetSymbolAddress((void**)&agg0, d_agg0);
    cudaGetSymbolAddress((void**)&deg,  d_deg);
    cudaGetSymbolAddress((void**)&gi,   d_gi);
    cudaGetSymbolAddress((void**)&Wc,   d_Wc);
    cudaGetSymbolAddress((void**)&bc,   d_bc);
    cudaGetSymbolAddress((void**)&Wcat, d_Wcat);
    cudaGetSymbolAddress((void**)&bcat, d_bcat);

    // one-time per launch: repacked weights + composed message->GRU weight
    repack<<<Hn * NC / 256, 256>>>(msg_W1, gru_Whh, msg_b1, gru_bhh, Wcat, bcat);
    gemm128<<<dim3(768/64, Hn/128), 256>>>(msg_W2, gru_Wih, nullptr, Wc, Hn, 768, Hn, 0, nullptr, nullptr);
    bck<<<96, 256>>>(msg_b2, gru_Wih, bc);

    // pre-MLP: h = relu(X@pre_W1+b1) @ pre_W2 + b2   (d_big reused as temp)
    gemm128<<<dim3(Hn/64, BN/128), 256>>>(X, pre_W1, pre_b1, big, BN, Hn, Fn, 1, nullptr, nullptr);
    gemm128<<<dim3(Hn/64, BN/128), 256>>>(big, pre_W2, pre_b2, h, BN, Hn, Hn, 0, nullptr, nullptr);

    for (int it = 0; it < Tn; it++) {
        // [hi+b1 | hj | gh+bhh] = h @ Wcat + bcat
        gemm128<<<dim3(NC/64, BN/128), 256>>>(h, Wcat, bcat, big, BN, NC, Hn, 0, nullptr, nullptr);
        // agg0, deg
        eagg<<<dim3(Nn/IT, Bn), 256>>>(big, adj, agg0, deg);
        // gi = agg0 @ Wc + deg*bc + bih
        gemm128<<<dim3(768/64, BN/128), 256>>>(agg0, Wc, gru_bih, gi, BN, 768, Hn, 0, deg, bc);
        // GRU update (in place on h)
        gru<<<BN, 256>>>(gi, big, h);
    }

    readout<<<1, 256>>>(h, ro_W1, ro_b1, ro_W2, ro_b2, (float*)d_out);
}